// round 1
// baseline (speedup 1.0000x reference)
#include <cuda_runtime.h>
#include <cuda_bf16.h>
#include <cstdint>

// Problem constants
#define BB 8
#define TT 2048
#define EE 1024
#define HDD 64
#define MM (BB * TT)          // 16384 rows
#define SCALE 0.125f          // HD^-0.5

// Scratch for q,k,v projections (fp32), 4 MB each
__device__ float g_q[MM * HDD];
__device__ float g_k[MM * HDD];
__device__ float g_v[MM * HDD];

// ---------------------------------------------------------------------------
// helpers
// ---------------------------------------------------------------------------
__device__ __forceinline__ float f2tff(float x) {
    uint32_t u;
    asm("cvt.rna.tf32.f32 %0, %1;" : "=r"(u) : "f"(x));
    return __uint_as_float(u);
}

__device__ __forceinline__ void mma8(float* c, const uint32_t* a, const uint32_t* b) {
    asm volatile(
        "mma.sync.aligned.m16n8k8.row.col.f32.tf32.tf32.f32 "
        "{%0,%1,%2,%3}, {%4,%5,%6,%7}, {%8,%9}, {%0,%1,%2,%3};"
        : "+f"(c[0]), "+f"(c[1]), "+f"(c[2]), "+f"(c[3])
        : "r"(a[0]), "r"(a[1]), "r"(a[2]), "r"(a[3]), "r"(b[0]), "r"(b[1]));
}

// ---------------------------------------------------------------------------
// Stage 1: QKV projection. C[16384, 64] = X[16384,1024] @ W[1024,64]
// grid (128, 3), block 256. CTA tile 128x64, K-chunk 32. tf32 mma.
// ---------------------------------------------------------------------------
#define XS_STRIDE 36   // 36 % 32 == 4 -> conflict-free A-frag loads
#define WS_STRIDE 68   // 68 % 32 == 4 -> conflict-free B-frag loads

__global__ __launch_bounds__(256) void qkv_kernel(
    const float* __restrict__ x,
    const float* __restrict__ Wq,
    const float* __restrict__ Wk,
    const float* __restrict__ Wv)
{
    __shared__ float Xs[128 * XS_STRIDE];
    __shared__ float Ws[32 * WS_STRIDE];

    const int tid  = threadIdx.x;
    const int warp = tid >> 5;
    const int lane = tid & 31;
    const int qd   = lane & 3;    // threadID in group
    const int gp   = lane >> 2;   // group id

    const int wm = (warp & 3) * 32;   // warp row offset within CTA tile
    const int wn = (warp >> 2) * 32;  // warp col offset (0 or 32)

    const float* W   = (blockIdx.y == 0) ? Wq : (blockIdx.y == 1) ? Wk : Wv;
    float*       out = (blockIdx.y == 0) ? g_q : (blockIdx.y == 1) ? g_k : g_v;

    const int row0 = blockIdx.x * 128;

    float acc[2][4][4];
#pragma unroll
    for (int mt = 0; mt < 2; mt++)
#pragma unroll
        for (int nt = 0; nt < 4; nt++)
#pragma unroll
            for (int i = 0; i < 4; i++) acc[mt][nt][i] = 0.0f;

    for (int kb = 0; kb < EE; kb += 32) {
        // load X tile [128 x 32], convert to tf32
        {
            const int r  = tid >> 3;
            const int c4 = (tid & 7) * 4;
#pragma unroll
            for (int p = 0; p < 4; p++) {
                float4 v = *(const float4*)&x[(size_t)(row0 + r + p * 32) * EE + kb + c4];
                float* dst = &Xs[(r + p * 32) * XS_STRIDE + c4];
                dst[0] = f2tff(v.x); dst[1] = f2tff(v.y);
                dst[2] = f2tff(v.z); dst[3] = f2tff(v.w);
            }
        }
        // load W tile [32 x 64], convert to tf32
        {
            const int r  = tid >> 4;
            const int c4 = (tid & 15) * 4;
#pragma unroll
            for (int p = 0; p < 2; p++) {
                float4 v = *(const float4*)&W[(size_t)(kb + r + p * 16) * HDD + c4];
                float* dst = &Ws[(r + p * 16) * WS_STRIDE + c4];
                dst[0] = f2tff(v.x); dst[1] = f2tff(v.y);
                dst[2] = f2tff(v.z); dst[3] = f2tff(v.w);
            }
        }
        __syncthreads();

#pragma unroll
        for (int ks = 0; ks < 4; ks++) {
            const int k0 = ks * 8;
            uint32_t a[2][4];
#pragma unroll
            for (int mt = 0; mt < 2; mt++) {
                const int r = wm + mt * 16 + gp;
                a[mt][0] = __float_as_uint(Xs[r * XS_STRIDE + k0 + qd]);
                a[mt][1] = __float_as_uint(Xs[(r + 8) * XS_STRIDE + k0 + qd]);
                a[mt][2] = __float_as_uint(Xs[r * XS_STRIDE + k0 + qd + 4]);
                a[mt][3] = __float_as_uint(Xs[(r + 8) * XS_STRIDE + k0 + qd + 4]);
            }
#pragma unroll
            for (int nt = 0; nt < 4; nt++) {
                uint32_t b[2];
                const int n = wn + nt * 8 + gp;
                b[0] = __float_as_uint(Ws[(k0 + qd) * WS_STRIDE + n]);
                b[1] = __float_as_uint(Ws[(k0 + qd + 4) * WS_STRIDE + n]);
                mma8(acc[0][nt], a[0], b);
                mma8(acc[1][nt], a[1], b);
            }
        }
        __syncthreads();
    }

    // epilogue
#pragma unroll
    for (int mt = 0; mt < 2; mt++) {
#pragma unroll
        for (int nt = 0; nt < 4; nt++) {
            const int r = row0 + wm + mt * 16 + gp;
            const int c = wn + nt * 8 + 2 * qd;
            *(float2*)&out[(size_t)r * HDD + c]       = make_float2(acc[mt][nt][0], acc[mt][nt][1]);
            *(float2*)&out[(size_t)(r + 8) * HDD + c] = make_float2(acc[mt][nt][2], acc[mt][nt][3]);
        }
    }
}

// ---------------------------------------------------------------------------
// Stage 2: causal flash attention over q/k/v scratch.
// grid (16, 8) = (q-tile, batch), block 256 (8 warps). Each warp owns 16 rows.
// ---------------------------------------------------------------------------
#define QS_STRIDE 68    // Q/K/V smem row stride (floats), 68 % 32 == 4
#define PS_STRIDE 132   // P smem row stride, 132 % 32 == 4
#define ATTN_SMEM_FLOATS (3 * 128 * QS_STRIDE + 128 * PS_STRIDE)
#define ATTN_SMEM_BYTES  (ATTN_SMEM_FLOATS * 4)   // 172032

__global__ __launch_bounds__(256, 1) void attn_kernel(float* __restrict__ out)
{
    extern __shared__ float sm[];
    float* Qs = sm;
    float* Ks = Qs + 128 * QS_STRIDE;
    float* Vs = Ks + 128 * QS_STRIDE;
    float* Ps = Vs + 128 * QS_STRIDE;

    const int tid  = threadIdx.x;
    const int warp = tid >> 5;
    const int lane = tid & 31;
    const int qd   = lane & 3;
    const int gp   = lane >> 2;

    const int qt = blockIdx.x;
    const int b  = blockIdx.y;

    // load Q tile [128 x 64] -> smem (tf32)
    {
        const float* qptr = g_q + ((size_t)b * TT + qt * 128) * HDD;
        const int r  = tid >> 4;
        const int c4 = (tid & 15) * 4;
#pragma unroll
        for (int p = 0; p < 8; p++) {
            float4 v = *(const float4*)&qptr[(size_t)(r + p * 16) * HDD + c4];
            float* dst = &Qs[(r + p * 16) * QS_STRIDE + c4];
            dst[0] = f2tff(v.x); dst[1] = f2tff(v.y);
            dst[2] = f2tff(v.z); dst[3] = f2tff(v.w);
        }
    }
    __syncthreads();

    // hoist Q A-fragments (warp's 16 rows, all 8 k-steps) into registers
    uint32_t qa[8][4];
    const int r0 = warp * 16 + gp;
#pragma unroll
    for (int ks = 0; ks < 8; ks++) {
        const int k0 = ks * 8;
        qa[ks][0] = __float_as_uint(Qs[r0 * QS_STRIDE + k0 + qd]);
        qa[ks][1] = __float_as_uint(Qs[(r0 + 8) * QS_STRIDE + k0 + qd]);
        qa[ks][2] = __float_as_uint(Qs[r0 * QS_STRIDE + k0 + qd + 4]);
        qa[ks][3] = __float_as_uint(Qs[(r0 + 8) * QS_STRIDE + k0 + qd + 4]);
    }

    float m0 = -1e30f, m1 = -1e30f, l0 = 0.0f, l1 = 0.0f;
    float o[8][4];
#pragma unroll
    for (int nt = 0; nt < 8; nt++)
#pragma unroll
        for (int i = 0; i < 4; i++) o[nt][i] = 0.0f;

    const int rg0 = qt * 128 + warp * 16 + gp;   // global row for r0

    for (int j = 0; j <= qt; j++) {
        __syncthreads();   // all warps done with previous K/V/P
        // load K,V tile j -> smem (tf32)
        {
            const float* kp = g_k + ((size_t)b * TT + j * 128) * HDD;
            const float* vp = g_v + ((size_t)b * TT + j * 128) * HDD;
            const int r  = tid >> 4;
            const int c4 = (tid & 15) * 4;
#pragma unroll
            for (int p = 0; p < 8; p++) {
                float4 kv = *(const float4*)&kp[(size_t)(r + p * 16) * HDD + c4];
                float4 vv = *(const float4*)&vp[(size_t)(r + p * 16) * HDD + c4];
                float* kd = &Ks[(r + p * 16) * QS_STRIDE + c4];
                float* vd = &Vs[(r + p * 16) * QS_STRIDE + c4];
                kd[0] = f2tff(kv.x); kd[1] = f2tff(kv.y);
                kd[2] = f2tff(kv.z); kd[3] = f2tff(kv.w);
                vd[0] = f2tff(vv.x); vd[1] = f2tff(vv.y);
                vd[2] = f2tff(vv.z); vd[3] = f2tff(vv.w);
            }
        }
        __syncthreads();

        // S[16 x 128] = Q_tile @ K_tile^T   (per warp)
        float s[16][4];
#pragma unroll
        for (int nt = 0; nt < 16; nt++)
#pragma unroll
            for (int i = 0; i < 4; i++) s[nt][i] = 0.0f;

#pragma unroll
        for (int ks = 0; ks < 8; ks++) {
            const int k0 = ks * 8;
#pragma unroll
            for (int nt = 0; nt < 16; nt++) {
                uint32_t bb[2];
                const int n = nt * 8 + gp;
                bb[0] = __float_as_uint(Ks[n * QS_STRIDE + k0 + qd]);
                bb[1] = __float_as_uint(Ks[n * QS_STRIDE + k0 + qd + 4]);
                mma8(s[nt], qa[ks], bb);
            }
        }

        // scale + causal mask (only diagonal tile needs masking)
        const bool diag = (j == qt);
#pragma unroll
        for (int nt = 0; nt < 16; nt++) {
            s[nt][0] *= SCALE; s[nt][1] *= SCALE;
            s[nt][2] *= SCALE; s[nt][3] *= SCALE;
            if (diag) {
                const int c = j * 128 + nt * 8 + 2 * qd;
                if (c     > rg0)     s[nt][0] = -1e30f;
                if (c + 1 > rg0)     s[nt][1] = -1e30f;
                if (c     > rg0 + 8) s[nt][2] = -1e30f;
                if (c + 1 > rg0 + 8) s[nt][3] = -1e30f;
            }
        }

        // row max over the 128 columns (per-thread 32 values + 4-lane shfl)
        float mx0 = -1e30f, mx1 = -1e30f;
#pragma unroll
        for (int nt = 0; nt < 16; nt++) {
            mx0 = fmaxf(mx0, fmaxf(s[nt][0], s[nt][1]));
            mx1 = fmaxf(mx1, fmaxf(s[nt][2], s[nt][3]));
        }
        mx0 = fmaxf(mx0, __shfl_xor_sync(0xffffffffu, mx0, 1));
        mx0 = fmaxf(mx0, __shfl_xor_sync(0xffffffffu, mx0, 2));
        mx1 = fmaxf(mx1, __shfl_xor_sync(0xffffffffu, mx1, 1));
        mx1 = fmaxf(mx1, __shfl_xor_sync(0xffffffffu, mx1, 2));

        const float nm0 = fmaxf(m0, mx0);
        const float nm1 = fmaxf(m1, mx1);
        const float a0 = __expf(m0 - nm0);
        const float a1 = __expf(m1 - nm1);
        m0 = nm0; m1 = nm1;

        float sum0 = 0.0f, sum1 = 0.0f;
#pragma unroll
        for (int nt = 0; nt < 16; nt++) {
            s[nt][0] = __expf(s[nt][0] - nm0);
            s[nt][1] = __expf(s[nt][1] - nm0);
            s[nt][2] = __expf(s[nt][2] - nm1);
            s[nt][3] = __expf(s[nt][3] - nm1);
            sum0 += s[nt][0] + s[nt][1];
            sum1 += s[nt][2] + s[nt][3];
        }
        sum0 += __shfl_xor_sync(0xffffffffu, sum0, 1);
        sum0 += __shfl_xor_sync(0xffffffffu, sum0, 2);
        sum1 += __shfl_xor_sync(0xffffffffu, sum1, 1);
        sum1 += __shfl_xor_sync(0xffffffffu, sum1, 2);
        l0 = l0 * a0 + sum0;
        l1 = l1 * a1 + sum1;

        // rescale O accumulators
#pragma unroll
        for (int nt = 0; nt < 8; nt++) {
            o[nt][0] *= a0; o[nt][1] *= a0;
            o[nt][2] *= a1; o[nt][3] *= a1;
        }

        // stage P (tf32) into smem — warp-private rows, only __syncwarp needed
#pragma unroll
        for (int nt = 0; nt < 16; nt++) {
            const int c = nt * 8 + 2 * qd;
            Ps[r0 * PS_STRIDE + c]           = f2tff(s[nt][0]);
            Ps[r0 * PS_STRIDE + c + 1]       = f2tff(s[nt][1]);
            Ps[(r0 + 8) * PS_STRIDE + c]     = f2tff(s[nt][2]);
            Ps[(r0 + 8) * PS_STRIDE + c + 1] = f2tff(s[nt][3]);
        }
        __syncwarp();

        // O[16 x 64] += P[16 x 128] @ V[128 x 64]
#pragma unroll
        for (int ks = 0; ks < 16; ks++) {
            const int k0 = ks * 8;
            uint32_t a[4];
            a[0] = __float_as_uint(Ps[r0 * PS_STRIDE + k0 + qd]);
            a[1] = __float_as_uint(Ps[(r0 + 8) * PS_STRIDE + k0 + qd]);
            a[2] = __float_as_uint(Ps[r0 * PS_STRIDE + k0 + qd + 4]);
            a[3] = __float_as_uint(Ps[(r0 + 8) * PS_STRIDE + k0 + qd + 4]);
#pragma unroll
            for (int nt = 0; nt < 8; nt++) {
                uint32_t bb[2];
                const int n = nt * 8 + gp;
                bb[0] = __float_as_uint(Vs[(k0 + qd) * QS_STRIDE + n]);
                bb[1] = __float_as_uint(Vs[(k0 + qd + 4) * QS_STRIDE + n]);
                mma8(o[nt], a, bb);
            }
        }
    }

    // epilogue: O / l -> out
    const float inv0 = 1.0f / l0;
    const float inv1 = 1.0f / l1;
    float* op = out + ((size_t)b * TT + qt * 128) * HDD;
    const int rr = warp * 16 + gp;
#pragma unroll
    for (int nt = 0; nt < 8; nt++) {
        const int c = nt * 8 + 2 * qd;
        *(float2*)&op[(size_t)rr * HDD + c]       = make_float2(o[nt][0] * inv0, o[nt][1] * inv0);
        *(float2*)&op[(size_t)(rr + 8) * HDD + c] = make_float2(o[nt][2] * inv1, o[nt][3] * inv1);
    }
}

// ---------------------------------------------------------------------------
// launch
// ---------------------------------------------------------------------------
extern "C" void kernel_launch(void* const* d_in, const int* in_sizes, int n_in,
                              void* d_out, int out_size)
{
    const float* x  = (const float*)d_in[0];
    const float* Wq = (const float*)d_in[1];
    const float* Wk = (const float*)d_in[2];
    const float* Wv = (const float*)d_in[3];
    float* out = (float*)d_out;

    qkv_kernel<<<dim3(MM / 128, 3), 256>>>(x, Wq, Wk, Wv);

    cudaFuncSetAttribute(attn_kernel, cudaFuncAttributeMaxDynamicSharedMemorySize,
                         ATTN_SMEM_BYTES);
    attn_kernel<<<dim3(TT / 128, BB), 256, ATTN_SMEM_BYTES>>>(out);
}

// round 2
// speedup vs baseline: 1.4210x; 1.4210x over previous
#include <cuda_runtime.h>
#include <cstdint>

// Problem constants
#define BB 8
#define TT 2048
#define EE 1024
#define HDD 64
#define MM (BB * TT)          // 16384 rows
#define SCALE 0.125f          // HD^-0.5

// Scratch for q,k,v projections (fp32), 4 MB each
__device__ float g_q[MM * HDD];
__device__ float g_k[MM * HDD];
__device__ float g_v[MM * HDD];
// Split-kv partials: [b][qt][chunk] x (128 rows x 64 cols) + per-row m,l
__device__ float g_po[BB * 16 * 4 * 128 * HDD];
__device__ float g_pm[BB * 16 * 4 * 128];
__device__ float g_pl[BB * 16 * 4 * 128];

// ---------------------------------------------------------------------------
// helpers
// ---------------------------------------------------------------------------
__device__ __forceinline__ float f2tff(float x) {
    uint32_t u;
    asm("cvt.rna.tf32.f32 %0, %1;" : "=r"(u) : "f"(x));
    return __uint_as_float(u);
}

__device__ __forceinline__ void mma8(float* c, const uint32_t* a, const uint32_t* b) {
    asm volatile(
        "mma.sync.aligned.m16n8k8.row.col.f32.tf32.tf32.f32 "
        "{%0,%1,%2,%3}, {%4,%5,%6,%7}, {%8,%9}, {%0,%1,%2,%3};"
        : "+f"(c[0]), "+f"(c[1]), "+f"(c[2]), "+f"(c[3])
        : "r"(a[0]), "r"(a[1]), "r"(a[2]), "r"(a[3]), "r"(b[0]), "r"(b[1]));
}

// ---------------------------------------------------------------------------
// Stage 1: fused QKV projection. CTA tile 128 rows x 192 cols (Q|K|V heads).
// grid 128, block 256 (8 warps: 2 row-halves x 4 col-blocks of 48).
// Register-double-buffered smem, ONE __syncthreads per 32-wide k-chunk.
// ---------------------------------------------------------------------------
#define XS_STRIDE 36          // 36 % 32 == 4 -> conflict-friendly
#define WS3_STRIDE 196        // 196 % 32 == 4
#define XS_BUF (128 * XS_STRIDE)
#define WS_BUF (32 * WS3_STRIDE)
#define QKV_SMEM_BYTES ((2 * XS_BUF + 2 * WS_BUF) * 4)   // 87040

__global__ __launch_bounds__(256) void qkv_kernel(
    const float* __restrict__ x,
    const float* __restrict__ Wq,
    const float* __restrict__ Wk,
    const float* __restrict__ Wv)
{
    extern __shared__ float sm[];
    float* Xs = sm;                     // [2][128*36]
    float* Ws = sm + 2 * XS_BUF;        // [2][32*196]

    const int tid  = threadIdx.x;
    const int warp = tid >> 5;
    const int lane = tid & 31;
    const int qd   = lane & 3;
    const int gp   = lane >> 2;
    const int wr   = warp & 1;          // row half (0/1) -> 64 rows
    const int wc   = warp >> 1;         // col block (0..3) -> 48 cols

    const int row0 = blockIdx.x * 128;
    const float* Wp0 = Wq;
    const float* Wp1 = Wk;
    const float* Wp2 = Wv;

    float acc[4][6][4];
#pragma unroll
    for (int mt = 0; mt < 4; mt++)
#pragma unroll
        for (int nt = 0; nt < 6; nt++)
#pragma unroll
            for (int i = 0; i < 4; i++) acc[mt][nt][i] = 0.0f;

    float4 xr[4];
    float4 wreg[3][2];

    // prefetch chunk 0
#pragma unroll
    for (int p = 0; p < 4; p++) {
        const int idx = tid + p * 256;
        const int r = idx >> 3, c4 = (idx & 7) * 4;
        xr[p] = *(const float4*)&x[(size_t)(row0 + r) * EE + c4];
    }
#pragma unroll
    for (int p = 0; p < 2; p++) {
        const int idx = tid + p * 256;
        const int r = idx >> 4, c4 = (idx & 15) * 4;
        wreg[0][p] = *(const float4*)&Wp0[(size_t)r * HDD + c4];
        wreg[1][p] = *(const float4*)&Wp1[(size_t)r * HDD + c4];
        wreg[2][p] = *(const float4*)&Wp2[(size_t)r * HDD + c4];
    }

    for (int kbi = 0; kbi < 32; kbi++) {
        float* Xb = Xs + (kbi & 1) * XS_BUF;
        float* Wb = Ws + (kbi & 1) * WS_BUF;

        // store prefetched regs -> smem (convert to tf32)
#pragma unroll
        for (int p = 0; p < 4; p++) {
            const int idx = tid + p * 256;
            const int r = idx >> 3, c4 = (idx & 7) * 4;
            float* d = &Xb[r * XS_STRIDE + c4];
            d[0] = f2tff(xr[p].x); d[1] = f2tff(xr[p].y);
            d[2] = f2tff(xr[p].z); d[3] = f2tff(xr[p].w);
        }
#pragma unroll
        for (int w = 0; w < 3; w++)
#pragma unroll
            for (int p = 0; p < 2; p++) {
                const int idx = tid + p * 256;
                const int r = idx >> 4, c4 = (idx & 15) * 4;
                float* d = &Wb[r * WS3_STRIDE + w * 64 + c4];
                d[0] = f2tff(wreg[w][p].x); d[1] = f2tff(wreg[w][p].y);
                d[2] = f2tff(wreg[w][p].z); d[3] = f2tff(wreg[w][p].w);
            }

        // prefetch next chunk
        if (kbi < 31) {
            const int kb = (kbi + 1) * 32;
#pragma unroll
            for (int p = 0; p < 4; p++) {
                const int idx = tid + p * 256;
                const int r = idx >> 3, c4 = (idx & 7) * 4;
                xr[p] = *(const float4*)&x[(size_t)(row0 + r) * EE + kb + c4];
            }
#pragma unroll
            for (int p = 0; p < 2; p++) {
                const int idx = tid + p * 256;
                const int r = idx >> 4, c4 = (idx & 15) * 4;
                wreg[0][p] = *(const float4*)&Wp0[(size_t)(kb + r) * HDD + c4];
                wreg[1][p] = *(const float4*)&Wp1[(size_t)(kb + r) * HDD + c4];
                wreg[2][p] = *(const float4*)&Wp2[(size_t)(kb + r) * HDD + c4];
            }
        }
        __syncthreads();   // single barrier per chunk (double-buffered smem)

#pragma unroll
        for (int ks = 0; ks < 4; ks++) {
            const int k0 = ks * 8;
            uint32_t a[4][4];
#pragma unroll
            for (int mt = 0; mt < 4; mt++) {
                const int r = wr * 64 + mt * 16 + gp;
                a[mt][0] = __float_as_uint(Xb[r * XS_STRIDE + k0 + qd]);
                a[mt][1] = __float_as_uint(Xb[(r + 8) * XS_STRIDE + k0 + qd]);
                a[mt][2] = __float_as_uint(Xb[r * XS_STRIDE + k0 + qd + 4]);
                a[mt][3] = __float_as_uint(Xb[(r + 8) * XS_STRIDE + k0 + qd + 4]);
            }
#pragma unroll
            for (int nt = 0; nt < 6; nt++) {
                uint32_t b[2];
                const int n = wc * 48 + nt * 8 + gp;
                b[0] = __float_as_uint(Wb[(k0 + qd) * WS3_STRIDE + n]);
                b[1] = __float_as_uint(Wb[(k0 + qd + 4) * WS3_STRIDE + n]);
#pragma unroll
                for (int mt = 0; mt < 4; mt++) mma8(acc[mt][nt], a[mt], b);
            }
        }
    }

    // epilogue: route each 8-col block to q/k/v head
#pragma unroll
    for (int mt = 0; mt < 4; mt++) {
#pragma unroll
        for (int nt = 0; nt < 6; nt++) {
            const int r = row0 + wr * 64 + mt * 16 + gp;
            const int col192 = wc * 48 + nt * 8 + 2 * qd;
            float* outp = (col192 < 64) ? g_q : (col192 < 128) ? g_k : g_v;
            const int c = col192 & 63;
            *(float2*)&outp[(size_t)r * HDD + c]       = make_float2(acc[mt][nt][0], acc[mt][nt][1]);
            *(float2*)&outp[(size_t)(r + 8) * HDD + c] = make_float2(acc[mt][nt][2], acc[mt][nt][3]);
        }
    }
}

// ---------------------------------------------------------------------------
// Stage 2: split-kv causal flash attention.
// Q tile 128 rows; kv chunks of 512 (8 tiles of 64). grid (40, 8), block 256.
// 104.4KB smem + <=128 regs -> 2 CTAs/SM.
// ---------------------------------------------------------------------------
#define QS 68                                  // smem row stride (floats)
#define ATTN_SMEM_BYTES ((128 * QS + 64 * QS + 64 * QS + 128 * QS) * 4)  // 104448

__global__ __launch_bounds__(256, 2) void attn_kernel(float* __restrict__ out)
{
    extern __shared__ float sm[];
    float* Qs = sm;                  // 128 x 64
    float* Ks = Qs + 128 * QS;       // 64 x 64
    float* Vs = Ks + 64 * QS;        // 64 x 64
    float* Ps = Vs + 64 * QS;        // 128 x 64

    const int tid  = threadIdx.x;
    const int warp = tid >> 5;
    const int lane = tid & 31;
    const int qd   = lane & 3;
    const int gp   = lane >> 2;
    const int b    = blockIdx.y;

    // map blockIdx.x -> (qt, chunk)
    int xx = blockIdx.x, qt = 0, ck = 0;
    for (qt = 0; qt < 16; qt++) {
        const int n = (qt + 4) >> 2;          // ceil((qt+1)/4)
        if (xx < n) { ck = xx; break; }
        xx -= n;
    }
    const int nc = (qt + 4) >> 2;
    const int j0 = ck * 8;
    const int j1 = min(ck * 8 + 8, 2 * (qt + 1));

    // load Q tile [128 x 64] -> smem (tf32)
    {
        const float* qptr = g_q + ((size_t)b * TT + qt * 128) * HDD;
#pragma unroll
        for (int p = 0; p < 8; p++) {
            const int idx = tid + p * 256;
            const int r = idx >> 4, c4 = (idx & 15) * 4;
            float4 v = *(const float4*)&qptr[(size_t)r * HDD + c4];
            float* d = &Qs[r * QS + c4];
            d[0] = f2tff(v.x); d[1] = f2tff(v.y);
            d[2] = f2tff(v.z); d[3] = f2tff(v.w);
        }
    }

    const int r0  = warp * 16 + gp;            // local row
    const int rg0 = qt * 128 + r0;             // global row

    float m0 = -1e30f, m1 = -1e30f, l0 = 0.0f, l1 = 0.0f;
    float o[8][4];
#pragma unroll
    for (int nt = 0; nt < 8; nt++)
#pragma unroll
        for (int i = 0; i < 4; i++) o[nt][i] = 0.0f;

    for (int j64 = j0; j64 < j1; j64++) {
        __syncthreads();   // previous tile fully consumed (also orders Q load, iter 0)
        {
            const float* kp = g_k + ((size_t)b * TT + j64 * 64) * HDD;
            const float* vp = g_v + ((size_t)b * TT + j64 * 64) * HDD;
#pragma unroll
            for (int p = 0; p < 4; p++) {
                const int idx = tid + p * 256;
                const int r = idx >> 4, c4 = (idx & 15) * 4;
                float4 kv = *(const float4*)&kp[(size_t)r * HDD + c4];
                float4 vv = *(const float4*)&vp[(size_t)r * HDD + c4];
                float* kd = &Ks[r * QS + c4];
                float* vd = &Vs[r * QS + c4];
                kd[0] = f2tff(kv.x); kd[1] = f2tff(kv.y);
                kd[2] = f2tff(kv.z); kd[3] = f2tff(kv.w);
                vd[0] = f2tff(vv.x); vd[1] = f2tff(vv.y);
                vd[2] = f2tff(vv.z); vd[3] = f2tff(vv.w);
            }
        }
        __syncthreads();

        // S[16 x 64] = Q rows @ K^T
        float s[8][4];
#pragma unroll
        for (int nt = 0; nt < 8; nt++)
#pragma unroll
            for (int i = 0; i < 4; i++) s[nt][i] = 0.0f;

#pragma unroll
        for (int ks = 0; ks < 8; ks++) {
            const int k0 = ks * 8;
            uint32_t a[4];
            a[0] = __float_as_uint(Qs[r0 * QS + k0 + qd]);
            a[1] = __float_as_uint(Qs[(r0 + 8) * QS + k0 + qd]);
            a[2] = __float_as_uint(Qs[r0 * QS + k0 + qd + 4]);
            a[3] = __float_as_uint(Qs[(r0 + 8) * QS + k0 + qd + 4]);
#pragma unroll
            for (int nt = 0; nt < 8; nt++) {
                uint32_t bb[2];
                const int n = nt * 8 + gp;
                bb[0] = __float_as_uint(Ks[n * QS + k0 + qd]);
                bb[1] = __float_as_uint(Ks[n * QS + k0 + qd + 4]);
                mma8(s[nt], a, bb);
            }
        }

        const bool diag = (j64 >= 2 * qt);
#pragma unroll
        for (int nt = 0; nt < 8; nt++) {
            s[nt][0] *= SCALE; s[nt][1] *= SCALE;
            s[nt][2] *= SCALE; s[nt][3] *= SCALE;
            if (diag) {
                const int c = j64 * 64 + nt * 8 + 2 * qd;
                if (c     > rg0)     s[nt][0] = -1e30f;
                if (c + 1 > rg0)     s[nt][1] = -1e30f;
                if (c     > rg0 + 8) s[nt][2] = -1e30f;
                if (c + 1 > rg0 + 8) s[nt][3] = -1e30f;
            }
        }

        float mx0 = -1e30f, mx1 = -1e30f;
#pragma unroll
        for (int nt = 0; nt < 8; nt++) {
            mx0 = fmaxf(mx0, fmaxf(s[nt][0], s[nt][1]));
            mx1 = fmaxf(mx1, fmaxf(s[nt][2], s[nt][3]));
        }
        mx0 = fmaxf(mx0, __shfl_xor_sync(0xffffffffu, mx0, 1));
        mx0 = fmaxf(mx0, __shfl_xor_sync(0xffffffffu, mx0, 2));
        mx1 = fmaxf(mx1, __shfl_xor_sync(0xffffffffu, mx1, 1));
        mx1 = fmaxf(mx1, __shfl_xor_sync(0xffffffffu, mx1, 2));

        const float nm0 = fmaxf(m0, mx0);
        const float nm1 = fmaxf(m1, mx1);
        const float a0 = __expf(m0 - nm0);
        const float a1 = __expf(m1 - nm1);
        m0 = nm0; m1 = nm1;

        float sum0 = 0.0f, sum1 = 0.0f;
#pragma unroll
        for (int nt = 0; nt < 8; nt++) {
            s[nt][0] = __expf(s[nt][0] - nm0);
            s[nt][1] = __expf(s[nt][1] - nm0);
            s[nt][2] = __expf(s[nt][2] - nm1);
            s[nt][3] = __expf(s[nt][3] - nm1);
            sum0 += s[nt][0] + s[nt][1];
            sum1 += s[nt][2] + s[nt][3];
        }
        sum0 += __shfl_xor_sync(0xffffffffu, sum0, 1);
        sum0 += __shfl_xor_sync(0xffffffffu, sum0, 2);
        sum1 += __shfl_xor_sync(0xffffffffu, sum1, 1);
        sum1 += __shfl_xor_sync(0xffffffffu, sum1, 2);
        l0 = l0 * a0 + sum0;
        l1 = l1 * a1 + sum1;

#pragma unroll
        for (int nt = 0; nt < 8; nt++) {
            o[nt][0] *= a0; o[nt][1] *= a0;
            o[nt][2] *= a1; o[nt][3] *= a1;
        }

        // stage P (tf32) into warp-private smem rows
#pragma unroll
        for (int nt = 0; nt < 8; nt++) {
            const int c = nt * 8 + 2 * qd;
            *(float2*)&Ps[r0 * QS + c]       = make_float2(f2tff(s[nt][0]), f2tff(s[nt][1]));
            *(float2*)&Ps[(r0 + 8) * QS + c] = make_float2(f2tff(s[nt][2]), f2tff(s[nt][3]));
        }
        __syncwarp();

        // O += P[16 x 64] @ V[64 x 64]
#pragma unroll
        for (int ks = 0; ks < 8; ks++) {
            const int k0 = ks * 8;
            uint32_t a[4];
            a[0] = __float_as_uint(Ps[r0 * QS + k0 + qd]);
            a[1] = __float_as_uint(Ps[(r0 + 8) * QS + k0 + qd]);
            a[2] = __float_as_uint(Ps[r0 * QS + k0 + qd + 4]);
            a[3] = __float_as_uint(Ps[(r0 + 8) * QS + k0 + qd + 4]);
#pragma unroll
            for (int nt = 0; nt < 8; nt++) {
                uint32_t bb[2];
                const int n = nt * 8 + gp;
                bb[0] = __float_as_uint(Vs[(k0 + qd) * QS + n]);
                bb[1] = __float_as_uint(Vs[(k0 + qd + 4) * QS + n]);
                mma8(o[nt], a, bb);
            }
        }
    }

    if (nc == 1) {
        // single chunk: write final output directly
        const float inv0 = 1.0f / l0;
        const float inv1 = 1.0f / l1;
        float* op = out + ((size_t)b * TT + qt * 128) * HDD;
#pragma unroll
        for (int nt = 0; nt < 8; nt++) {
            const int c = nt * 8 + 2 * qd;
            *(float2*)&op[(size_t)r0 * HDD + c]       = make_float2(o[nt][0] * inv0, o[nt][1] * inv0);
            *(float2*)&op[(size_t)(r0 + 8) * HDD + c] = make_float2(o[nt][2] * inv1, o[nt][3] * inv1);
        }
    } else {
        // write partials for combine
        const int pidx = (b * 16 + qt) * 4 + ck;
        float* po = g_po + (size_t)pidx * 128 * HDD;
#pragma unroll
        for (int nt = 0; nt < 8; nt++) {
            const int c = nt * 8 + 2 * qd;
            *(float2*)&po[(size_t)r0 * HDD + c]       = make_float2(o[nt][0], o[nt][1]);
            *(float2*)&po[(size_t)(r0 + 8) * HDD + c] = make_float2(o[nt][2], o[nt][3]);
        }
        if (qd == 0) {
            g_pm[pidx * 128 + r0]     = m0;
            g_pm[pidx * 128 + r0 + 8] = m1;
            g_pl[pidx * 128 + r0]     = l0;
            g_pl[pidx * 128 + r0 + 8] = l1;
        }
    }
}

// ---------------------------------------------------------------------------
// Stage 3: combine split-kv partials. grid (12, 8) -> qt in [4, 15].
// ---------------------------------------------------------------------------
__global__ __launch_bounds__(256) void combine_kernel(float* __restrict__ out)
{
    const int qt  = blockIdx.x + 4;
    const int b   = blockIdx.y;
    const int nc  = (qt + 4) >> 2;       // 2..4
    const int tid = threadIdx.x;
    const int r    = tid >> 1;           // 0..127
    const int half = (tid & 1) * 32;
    const int base = (b * 16 + qt) * 4;

    float m[4], l[4], w[4];
    float mstar = -1e30f;
#pragma unroll 4
    for (int c = 0; c < nc; c++) {
        m[c] = g_pm[(base + c) * 128 + r];
        l[c] = g_pl[(base + c) * 128 + r];
        mstar = fmaxf(mstar, m[c]);
    }
    float lstar = 0.0f;
#pragma unroll 4
    for (int c = 0; c < nc; c++) {
        w[c] = __expf(m[c] - mstar);
        lstar += w[c] * l[c];
    }
    const float inv = 1.0f / lstar;
#pragma unroll 4
    for (int c = 0; c < nc; c++) w[c] *= inv;

    float* op = out + ((size_t)b * TT + qt * 128 + r) * HDD + half;
#pragma unroll
    for (int g = 0; g < 8; g++) {
        float4 acc = make_float4(0.f, 0.f, 0.f, 0.f);
#pragma unroll 4
        for (int c = 0; c < nc; c++) {
            const float4 v = *(const float4*)&g_po[(size_t)(base + c) * 128 * HDD + r * HDD + half + g * 4];
            acc.x += w[c] * v.x; acc.y += w[c] * v.y;
            acc.z += w[c] * v.z; acc.w += w[c] * v.w;
        }
        *(float4*)&op[g * 4] = acc;
    }
}

// ---------------------------------------------------------------------------
// launch
// ---------------------------------------------------------------------------
extern "C" void kernel_launch(void* const* d_in, const int* in_sizes, int n_in,
                              void* d_out, int out_size)
{
    const float* x  = (const float*)d_in[0];
    const float* Wq = (const float*)d_in[1];
    const float* Wk = (const float*)d_in[2];
    const float* Wv = (const float*)d_in[3];
    float* out = (float*)d_out;

    cudaFuncSetAttribute(qkv_kernel, cudaFuncAttributeMaxDynamicSharedMemorySize,
                         QKV_SMEM_BYTES);
    qkv_kernel<<<MM / 128, 256, QKV_SMEM_BYTES>>>(x, Wq, Wk, Wv);

    cudaFuncSetAttribute(attn_kernel, cudaFuncAttributeMaxDynamicSharedMemorySize,
                         ATTN_SMEM_BYTES);
    attn_kernel<<<dim3(40, 8), 256, ATTN_SMEM_BYTES>>>(out);

    combine_kernel<<<dim3(12, 8), 256>>>(out);
}